// round 2
// baseline (speedup 1.0000x reference)
#include <cuda_runtime.h>
#include <cstddef>

// GCN 2-layer: out = A_n(relu(A_n(x W1)+b1) W2)+b2,  A_n = D^-1/2 (A+I) D^-1/2
// N=100000, E=3.2M, DIN=128, DH=32, DOUT=2
// NOTE: edge_index arrives as int32 (JAX default x64-disabled demotes int64).

static constexpr int NMAX  = 100000;
static constexpr int D_IN  = 128;
static constexpr int D_H   = 32;
static constexpr int D_OUT = 2;

// Scratch (allocation-free rule: __device__ globals), 16B-aligned for v4 ops.
__device__ __align__(16) float g_deg [NMAX];                 // deg -> dinv (in place)
__device__ __align__(16) float g_m1s [(size_t)NMAX * D_H];   // (x@W1)*dinv[row]
__device__ __align__(16) float g_agg1[(size_t)NMAX * D_H];   // layer-1 aggregate
__device__ __align__(16) float g_p2  [(size_t)NMAX * D_OUT]; // (relu(agg1+b1)@W2)*dinv[row]

__device__ __forceinline__ void red_add_v4(float* p, float4 v) {
    asm volatile("red.global.add.v4.f32 [%0], {%1,%2,%3,%4};"
                 :: "l"(p), "f"(v.x), "f"(v.y), "f"(v.z), "f"(v.w) : "memory");
}
__device__ __forceinline__ void red_add_v2(float* p, float a, float b) {
    asm volatile("red.global.add.v2.f32 [%0], {%1,%2};"
                 :: "l"(p), "f"(a), "f"(b) : "memory");
}

// ---- degree / normalization -------------------------------------------------
__global__ void k_init_deg(int n) {
    int i = blockIdx.x * blockDim.x + threadIdx.x;
    if (i < n) g_deg[i] = 1.0f;   // self loop contributes 1
}

__global__ void k_deg(const int* __restrict__ dst, int E) {
    int e = blockIdx.x * blockDim.x + threadIdx.x;
    if (e < E) atomicAdd(&g_deg[dst[e]], 1.0f);        // ptxas -> RED (no return)
}

__global__ void k_dinv(int n) {
    int i = blockIdx.x * blockDim.x + threadIdx.x;
    if (i < n) g_deg[i] = rsqrtf(g_deg[i]);            // deg >= 1 always
}

// ---- layer 1 GEMM: m1s = (x@W1)*dinv,  agg1 init = m1s*dinv (self loop) ----
// 256 thr/block = 8 warps; each warp computes 4 rows (register-blocked over W).
__global__ void k_gemm1(const float* __restrict__ x, const float* __restrict__ W1, int n) {
    __shared__ float  sW[D_IN * D_H];      // 16 KB
    __shared__ float4 sx[8][4][D_IN / 4];  // 16 KB: [warp][row][vec4]
    int tid = threadIdx.x;
    for (int i = tid; i < D_IN * D_H; i += 256) sW[i] = W1[i];
    __syncthreads();

    int warp = tid >> 5, lane = tid & 31;
    int row0 = blockIdx.x * 32 + warp * 4;

    #pragma unroll
    for (int r = 0; r < 4; r++) {
        int row = row0 + r;
        if (row < n)
            sx[warp][r][lane] = ((const float4*)(x + (size_t)row * D_IN))[lane];
    }
    __syncwarp();

    const float* sxf = (const float*)&sx[warp][0][0];   // [4][128]
    float acc0 = 0.f, acc1 = 0.f, acc2 = 0.f, acc3 = 0.f;
    #pragma unroll 8
    for (int k = 0; k < D_IN; k++) {
        float wv = sW[k * D_H + lane];     // conflict-free: lane-consecutive
        acc0 += sxf[0 * D_IN + k] * wv;    // broadcasts: conflict-free
        acc1 += sxf[1 * D_IN + k] * wv;
        acc2 += sxf[2 * D_IN + k] * wv;
        acc3 += sxf[3 * D_IN + k] * wv;
    }
    float acc[4] = {acc0, acc1, acc2, acc3};
    #pragma unroll
    for (int r = 0; r < 4; r++) {
        int row = row0 + r;
        if (row < n) {
            float dv = g_deg[row];
            float ms = acc[r] * dv;
            g_m1s [(size_t)row * D_H + lane] = ms;       // message, pre-scaled by dinv[src]
            g_agg1[(size_t)row * D_H + lane] = ms * dv;  // self-loop term dinv^2 * m1
        }
    }
}

// ---- layer 1 scatter: agg1[d] += m1s[s] * dinv[d] --------------------------
// 8 threads per edge, each owns one float4 chunk of the 32-float message.
__global__ void k_scatter1(const int* __restrict__ src,
                           const int* __restrict__ dst, long long E) {
    long long t = (long long)blockIdx.x * blockDim.x + threadIdx.x;
    long long e = t >> 3;
    int q = (int)(t & 7);
    if (e >= E) return;
    int s = __ldg(&src[e]);
    int d = __ldg(&dst[e]);
    float c = __ldg((const float*)&g_deg[d]);           // dinv[dst]
    float4 v = ((const float4*)(g_m1s + (size_t)s * D_H))[q];   // 1 L2 line per edge
    v.x *= c; v.y *= c; v.z *= c; v.w *= c;
    red_add_v4(g_agg1 + (size_t)d * D_H + q * 4, v);
}

// ---- layer 2 node: h=relu(agg1+b1); p=h@W2*dinv; out init = b2 + p*dinv ----
__global__ void k_layer2(const float* __restrict__ b1, const float* __restrict__ W2,
                         const float* __restrict__ b2, float* __restrict__ out, int n) {
    __shared__ float sb1[D_H], sW2[D_H * D_OUT], sb2[D_OUT];
    if (threadIdx.x < D_H)         sb1[threadIdx.x] = b1[threadIdx.x];
    if (threadIdx.x < D_H * D_OUT) sW2[threadIdx.x] = W2[threadIdx.x];
    if (threadIdx.x < D_OUT)       sb2[threadIdx.x] = b2[threadIdx.x];
    __syncthreads();
    int i = blockIdx.x * blockDim.x + threadIdx.x;
    if (i >= n) return;

    const float4* a = (const float4*)(g_agg1 + (size_t)i * D_H);
    float p0 = 0.f, p1 = 0.f;
    #pragma unroll
    for (int q = 0; q < 8; q++) {
        float4 v = a[q];
        float h0 = fmaxf(v.x + sb1[q * 4 + 0], 0.f);
        float h1 = fmaxf(v.y + sb1[q * 4 + 1], 0.f);
        float h2 = fmaxf(v.z + sb1[q * 4 + 2], 0.f);
        float h3 = fmaxf(v.w + sb1[q * 4 + 3], 0.f);
        p0 += h0 * sW2[(q * 4 + 0) * 2 + 0] + h1 * sW2[(q * 4 + 1) * 2 + 0]
            + h2 * sW2[(q * 4 + 2) * 2 + 0] + h3 * sW2[(q * 4 + 3) * 2 + 0];
        p1 += h0 * sW2[(q * 4 + 0) * 2 + 1] + h1 * sW2[(q * 4 + 1) * 2 + 1]
            + h2 * sW2[(q * 4 + 2) * 2 + 1] + h3 * sW2[(q * 4 + 3) * 2 + 1];
    }
    float dv = g_deg[i];
    float q0 = p0 * dv, q1 = p1 * dv;          // pre-scale by dinv[src]
    g_p2[(size_t)i * 2 + 0] = q0;
    g_p2[(size_t)i * 2 + 1] = q1;
    out[(size_t)i * 2 + 0] = sb2[0] + q0 * dv; // self-loop + bias
    out[(size_t)i * 2 + 1] = sb2[1] + q1 * dv;
}

// ---- layer 2 scatter: out[d] += p2[s] * dinv[d] ----------------------------
__global__ void k_scatter2(const int* __restrict__ src,
                           const int* __restrict__ dst, int E,
                           float* __restrict__ out) {
    int e = blockIdx.x * blockDim.x + threadIdx.x;
    if (e >= E) return;
    int s = __ldg(&src[e]);
    int d = __ldg(&dst[e]);
    float c = __ldg((const float*)&g_deg[d]);
    float2 p = *(const float2*)(g_p2 + (size_t)s * 2);
    red_add_v2(out + (size_t)d * 2, p.x * c, p.y * c);
}

extern "C" void kernel_launch(void* const* d_in, const int* in_sizes, int n_in,
                              void* d_out, int out_size) {
    const float* x   = (const float*)d_in[0];
    const int*   ei  = (const int*)d_in[1];     // int32 (JAX x64 disabled)
    const float* W1  = (const float*)d_in[2];
    const float* b1  = (const float*)d_in[3];
    const float* W2  = (const float*)d_in[4];
    const float* b2  = (const float*)d_in[5];
    float*       out = (float*)d_out;

    int n = in_sizes[0] / D_IN;
    int E = in_sizes[1] / 2;
    const int* src = ei;
    const int* dst = ei + E;

    k_init_deg<<<(n + 255) / 256, 256>>>(n);
    k_deg     <<<(E + 255) / 256, 256>>>(dst, E);
    k_dinv    <<<(n + 255) / 256, 256>>>(n);
    k_gemm1   <<<(n + 31) / 32, 256>>>(x, W1, n);
    long long work1 = (long long)E * 8;
    k_scatter1<<<(int)((work1 + 255) / 256), 256>>>(src, dst, (long long)E);
    k_layer2  <<<(n + 255) / 256, 256>>>(b1, W2, b2, out, n);
    k_scatter2<<<(E + 255) / 256, 256>>>(src, dst, E, out);
}

// round 5
// speedup vs baseline: 1.0329x; 1.0329x over previous
#include <cuda_runtime.h>
#include <cstddef>

// GCN 2-layer: out = A_n(relu(A_n(x W1)+b1) W2)+b2,  A_n = D^-1/2 (A+I) D^-1/2
// N=100000, E=3.2M, DIN=128, DH=32, DOUT=2
// edge_index arrives as int32 (JAX x64 disabled).

static constexpr int NMAX  = 100000;
static constexpr int D_IN  = 128;
static constexpr int D_H   = 32;
static constexpr int D_OUT = 2;

__device__ __align__(16) float g_deg [NMAX];
__device__ __align__(16) float g_m1s [(size_t)NMAX * D_H];
__device__ __align__(16) float g_agg1[(size_t)NMAX * D_H];
__device__ __align__(16) float g_p2  [(size_t)NMAX * D_OUT];

__device__ __forceinline__ void red_add_v4(float* p, float4 v) {
    asm volatile("red.global.add.v4.f32 [%0], {%1,%2,%3,%4};"
                 :: "l"(p), "f"(v.x), "f"(v.y), "f"(v.z), "f"(v.w) : "memory");
}
__device__ __forceinline__ void red_add_v2(float* p, float a, float b) {
    asm volatile("red.global.add.v2.f32 [%0], {%1,%2};"
                 :: "l"(p), "f"(a), "f"(b) : "memory");
}

// ---- degree / normalization -------------------------------------------------
__global__ void k_init_deg(int n) {
    int i = blockIdx.x * blockDim.x + threadIdx.x;
    if (i < n) g_deg[i] = 1.0f;   // self loop contributes 1
}

__global__ void k_deg(const int* __restrict__ dst, int E) {
    int e = blockIdx.x * blockDim.x + threadIdx.x;
    if (e < E) atomicAdd(&g_deg[dst[e]], 1.0f);
}

__global__ void k_dinv(int n) {
    int i = blockIdx.x * blockDim.x + threadIdx.x;
    if (i < n) g_deg[i] = rsqrtf(g_deg[i]);
}

// ---- layer 1 GEMM: m1s = (x@W1)*dinv,  agg1 init = m1s*dinv (self loop) ----
// 8 warps/block, each warp computes 8 rows x 32 cols.
// Inner iter (4 k-steps): 8 broadcast LDS.128 (x) + 4 LDS.32 (W) = 12 crossbar
// phases vs 32 FFMA = 16 issue cyc -> FFMA-bound.
__global__ void __launch_bounds__(256) k_gemm1(const float* __restrict__ x,
                                               const float* __restrict__ W1, int n) {
    __shared__ float  sW[D_IN * D_H];            // 16 KB
    __shared__ float4 sx[8][8][D_IN / 4];        // 32 KB: [warp][row][k4]
    int tid = threadIdx.x;
    for (int i = tid; i < D_IN * D_H; i += 256) sW[i] = W1[i];

    int warp = tid >> 5, lane = tid & 31;
    int row0 = blockIdx.x * 64 + warp * 8;

    #pragma unroll
    for (int r = 0; r < 8; r++) {
        int row = row0 + r;
        if (row < n)
            sx[warp][r][lane] = ((const float4*)(x + (size_t)row * D_IN))[lane];
    }
    __syncthreads();   // covers both sW and sx

    float acc[8] = {0.f, 0.f, 0.f, 0.f, 0.f, 0.f, 0.f, 0.f};
    #pragma unroll 4
    for (int k4 = 0; k4 < D_IN / 4; k4++) {
        float w0 = sW[(k4 * 4 + 0) * D_H + lane];
        float w1 = sW[(k4 * 4 + 1) * D_H + lane];
        float w2 = sW[(k4 * 4 + 2) * D_H + lane];
        float w3 = sW[(k4 * 4 + 3) * D_H + lane];
        #pragma unroll
        for (int r = 0; r < 8; r++) {
            float4 xv = sx[warp][r][k4];         // 16B broadcast
            acc[r] = fmaf(xv.x, w0, acc[r]);
            acc[r] = fmaf(xv.y, w1, acc[r]);
            acc[r] = fmaf(xv.z, w2, acc[r]);
            acc[r] = fmaf(xv.w, w3, acc[r]);
        }
    }
    #pragma unroll
    for (int r = 0; r < 8; r++) {
        int row = row0 + r;
        if (row < n) {
            float dv = g_deg[row];
            float ms = acc[r] * dv;
            g_m1s [(size_t)row * D_H + lane] = ms;       // pre-scaled by dinv[src]
            g_agg1[(size_t)row * D_H + lane] = ms * dv;  // self-loop term
        }
    }
}

// ---- layer 1 scatter: agg1[d] += m1s[s] * dinv[d] --------------------------
// 8 lanes per edge: each 128B row gather / RED coalesces into 1 wavefront.
__global__ void k_scatter1(const int* __restrict__ src,
                           const int* __restrict__ dst, long long E) {
    long long t = (long long)blockIdx.x * blockDim.x + threadIdx.x;
    long long e = t >> 3;
    int q = (int)(t & 7);
    if (e >= E) return;
    int s = __ldg(&src[e]);
    int d = __ldg(&dst[e]);
    float c = __ldg((const float*)&g_deg[d]);
    float4 v = ((const float4*)(g_m1s + (size_t)s * D_H))[q];
    v.x *= c; v.y *= c; v.z *= c; v.w *= c;
    red_add_v4(g_agg1 + (size_t)d * D_H + q * 4, v);
}

// ---- layer 2 node: h=relu(agg1+b1); p=h@W2*dinv; out init = b2 + p*dinv ----
__global__ void k_layer2(const float* __restrict__ b1, const float* __restrict__ W2,
                         const float* __restrict__ b2, float* __restrict__ out, int n) {
    __shared__ float sb1[D_H], sW2[D_H * D_OUT], sb2[D_OUT];
    if (threadIdx.x < D_H)         sb1[threadIdx.x] = b1[threadIdx.x];
    if (threadIdx.x < D_H * D_OUT) sW2[threadIdx.x] = W2[threadIdx.x];
    if (threadIdx.x < D_OUT)       sb2[threadIdx.x] = b2[threadIdx.x];
    __syncthreads();
    int i = blockIdx.x * blockDim.x + threadIdx.x;
    if (i >= n) return;

    const float4* a = (const float4*)(g_agg1 + (size_t)i * D_H);
    float p0 = 0.f, p1 = 0.f;
    #pragma unroll
    for (int q = 0; q < 8; q++) {
        float4 v = a[q];
        float h0 = fmaxf(v.x + sb1[q * 4 + 0], 0.f);
        float h1 = fmaxf(v.y + sb1[q * 4 + 1], 0.f);
        float h2 = fmaxf(v.z + sb1[q * 4 + 2], 0.f);
        float h3 = fmaxf(v.w + sb1[q * 4 + 3], 0.f);
        p0 += h0 * sW2[(q * 4 + 0) * 2 + 0] + h1 * sW2[(q * 4 + 1) * 2 + 0]
            + h2 * sW2[(q * 4 + 2) * 2 + 0] + h3 * sW2[(q * 4 + 3) * 2 + 0];
        p1 += h0 * sW2[(q * 4 + 0) * 2 + 1] + h1 * sW2[(q * 4 + 1) * 2 + 1]
            + h2 * sW2[(q * 4 + 2) * 2 + 1] + h3 * sW2[(q * 4 + 3) * 2 + 1];
    }
    float dv = g_deg[i];
    float q0 = p0 * dv, q1 = p1 * dv;
    g_p2[(size_t)i * 2 + 0] = q0;
    g_p2[(size_t)i * 2 + 1] = q1;
    out[(size_t)i * 2 + 0] = sb2[0] + q0 * dv;
    out[(size_t)i * 2 + 1] = sb2[1] + q1 * dv;
}

// ---- layer 2 scatter: out[d] += p2[s] * dinv[d] ----------------------------
__global__ void k_scatter2(const int* __restrict__ src,
                           const int* __restrict__ dst, int E,
                           float* __restrict__ out) {
    int e = blockIdx.x * blockDim.x + threadIdx.x;
    if (e >= E) return;
    int s = __ldg(&src[e]);
    int d = __ldg(&dst[e]);
    float c = __ldg((const float*)&g_deg[d]);
    float2 p = *(const float2*)(g_p2 + (size_t)s * 2);
    red_add_v2(out + (size_t)d * 2, p.x * c, p.y * c);
}

extern "C" void kernel_launch(void* const* d_in, const int* in_sizes, int n_in,
                              void* d_out, int out_size) {
    const float* x   = (const float*)d_in[0];
    const int*   ei  = (const int*)d_in[1];
    const float* W1  = (const float*)d_in[2];
    const float* b1  = (const float*)d_in[3];
    const float* W2  = (const float*)d_in[4];
    const float* b2  = (const float*)d_in[5];
    float*       out = (float*)d_out;

    int n = in_sizes[0] / D_IN;
    int E = in_sizes[1] / 2;
    const int* src = ei;
    const int* dst = ei + E;

    k_init_deg<<<(n + 255) / 256, 256>>>(n);
    k_deg     <<<(E + 255) / 256, 256>>>(dst, E);
    k_dinv    <<<(n + 255) / 256, 256>>>(n);
    k_gemm1   <<<(n + 63) / 64, 256>>>(x, W1, n);
    long long work1 = (long long)E * 8;
    k_scatter1<<<(int)((work1 + 255) / 256), 256>>>(src, dst, (long long)E);
    k_layer2  <<<(n + 255) / 256, 256>>>(b1, W2, b2, out, n);
    k_scatter2<<<(E + 255) / 256, 256>>>(src, dst, E, out);
}

// round 6
// speedup vs baseline: 1.0610x; 1.0272x over previous
#include <cuda_runtime.h>
#include <cstddef>

// GCN 2-layer: out = A_n(relu(A_n(x W1)+b1) W2)+b2,  A_n = D^-1/2 (A+I) D^-1/2
// N=100000, E=3.2M, DIN=128, DH=32, DOUT=2
// edge_index arrives as int32 (JAX x64 disabled).

static constexpr int NMAX  = 100000;
static constexpr int D_IN  = 128;
static constexpr int D_H   = 32;
static constexpr int D_OUT = 2;

__device__ __align__(16) float g_deg [NMAX];
__device__ __align__(16) float g_m1s [(size_t)NMAX * D_H];
__device__ __align__(16) float g_agg1[(size_t)NMAX * D_H];
__device__ __align__(16) float g_p2  [(size_t)NMAX * D_OUT];

__device__ __forceinline__ void red_add_v4(float* p, float4 v) {
    asm volatile("red.global.add.v4.f32 [%0], {%1,%2,%3,%4};"
                 :: "l"(p), "f"(v.x), "f"(v.y), "f"(v.z), "f"(v.w) : "memory");
}
__device__ __forceinline__ void red_add_v2(float* p, float a, float b) {
    asm volatile("red.global.add.v2.f32 [%0], {%1,%2};"
                 :: "l"(p), "f"(a), "f"(b) : "memory");
}
// Packed dual FMA: acc(f32x2) += a(f32x2) * b(f32x2)   -> SASS FFMA2
__device__ __forceinline__ void fma2(unsigned long long& acc,
                                     unsigned long long a, unsigned long long b) {
    asm("fma.rn.f32x2 %0, %1, %2, %0;" : "+l"(acc) : "l"(a), "l"(b));
}

// ---- degree / normalization -------------------------------------------------
__global__ void k_init_deg(int n) {
    int i = blockIdx.x * blockDim.x + threadIdx.x;
    if (i < n) g_deg[i] = 1.0f;   // self loop contributes 1
}

__global__ void k_deg(const int* __restrict__ dst, int E) {
    int e = blockIdx.x * blockDim.x + threadIdx.x;
    if (e < E) atomicAdd(&g_deg[dst[e]], 1.0f);
}

__global__ void k_dinv(int n) {
    int i = blockIdx.x * blockDim.x + threadIdx.x;
    if (i < n) g_deg[i] = rsqrtf(g_deg[i]);
}

// ---- layer 1 GEMM: m1s = (x@W1)*dinv,  agg1 init = m1s*dinv (self loop) ----
// 8 warps/block, warp computes 8 rows x 32 cols with packed f32x2 FFMA:
// acc2 = {sum over even k, sum over odd k}. Per k4-block per warp:
// 8 LDS.128 (x, broadcast) + 2 LDS.64 (W pairs, conflict-free) + 16 FFMA2.
__global__ void __launch_bounds__(256) k_gemm1(const float* __restrict__ x,
                                               const float* __restrict__ W1, int n) {
    __shared__ float  sWp[D_IN * D_H];       // 16 KB, k-pair interleaved transposed W
    __shared__ float4 sx[8][8][D_IN / 4];    // 32 KB: [warp][row][k4]
    int tid = threadIdx.x;
    // sWp pair layout: element {W[2k2][c], W[2k2+1][c]} at float offset k2*64 + c*2
    for (int i = tid; i < D_IN * D_H; i += 256) {
        int k = i >> 5, c = i & 31;          // W1 row-major [k][c]
        sWp[(k >> 1) * 64 + c * 2 + (k & 1)] = W1[i];
    }

    int warp = tid >> 5, lane = tid & 31;
    int row0 = blockIdx.x * 64 + warp * 8;

    #pragma unroll
    for (int r = 0; r < 8; r++) {
        int row = row0 + r;
        if (row < n)
            sx[warp][r][lane] = ((const float4*)(x + (size_t)row * D_IN))[lane];
    }
    __syncthreads();   // covers both sWp and sx

    const ulonglong2* sxp = (const ulonglong2*)&sx[warp][0][0];  // [8 rows][32 k4]
    const unsigned long long* sWq = (const unsigned long long*)sWp; // [64 k2][32 c]

    unsigned long long acc[8] = {0ull,0ull,0ull,0ull,0ull,0ull,0ull,0ull};
    #pragma unroll 4
    for (int k4 = 0; k4 < D_IN / 4; k4++) {
        unsigned long long w01 = sWq[(k4 * 2 + 0) * 32 + lane]; // {W[4k4+0][c],W[4k4+1][c]}
        unsigned long long w23 = sWq[(k4 * 2 + 1) * 32 + lane]; // {W[4k4+2][c],W[4k4+3][c]}
        #pragma unroll
        for (int r = 0; r < 8; r++) {
            ulonglong2 xp = sxp[r * 32 + k4]; // .x={x[k],x[k+1]} .y={x[k+2],x[k+3]}
            fma2(acc[r], xp.x, w01);
            fma2(acc[r], xp.y, w23);
        }
    }
    #pragma unroll
    for (int r = 0; r < 8; r++) {
        int row = row0 + r;
        if (row < n) {
            float lo = __uint_as_float((unsigned)(acc[r] & 0xffffffffull));
            float hi = __uint_as_float((unsigned)(acc[r] >> 32));
            float dv = g_deg[row];
            float ms = (lo + hi) * dv;
            g_m1s [(size_t)row * D_H + lane] = ms;       // pre-scaled by dinv[src]
            g_agg1[(size_t)row * D_H + lane] = ms * dv;  // self-loop term
        }
    }
}

// ---- layer 1 scatter: agg1[d] += m1s[s] * dinv[d] --------------------------
// 8 lanes per edge: each 128B row gather / RED coalesces into 1 wavefront.
__global__ void k_scatter1(const int* __restrict__ src,
                           const int* __restrict__ dst, long long E) {
    long long t = (long long)blockIdx.x * blockDim.x + threadIdx.x;
    long long e = t >> 3;
    int q = (int)(t & 7);
    if (e >= E) return;
    int s = __ldg(&src[e]);
    int d = __ldg(&dst[e]);
    float c = __ldg((const float*)&g_deg[d]);
    float4 v = ((const float4*)(g_m1s + (size_t)s * D_H))[q];
    v.x *= c; v.y *= c; v.z *= c; v.w *= c;
    red_add_v4(g_agg1 + (size_t)d * D_H + q * 4, v);
}

// ---- layer 2 node: h=relu(agg1+b1); p=h@W2*dinv; out init = b2 + p*dinv ----
__global__ void k_layer2(const float* __restrict__ b1, const float* __restrict__ W2,
                         const float* __restrict__ b2, float* __restrict__ out, int n) {
    __shared__ float sb1[D_H], sW2[D_H * D_OUT], sb2[D_OUT];
    if (threadIdx.x < D_H)         sb1[threadIdx.x] = b1[threadIdx.x];
    if (threadIdx.x < D_H * D_OUT) sW2[threadIdx.x] = W2[threadIdx.x];
    if (threadIdx.x < D_OUT)       sb2[threadIdx.x] = b2[threadIdx.x];
    __syncthreads();
    int i = blockIdx.x * blockDim.x + threadIdx.x;
    if (i >= n) return;

    const float4* a = (const float4*)(g_agg1 + (size_t)i * D_H);
    float p0 = 0.f, p1 = 0.f;
    #pragma unroll
    for (int q = 0; q < 8; q++) {
        float4 v = a[q];
        float h0 = fmaxf(v.x + sb1[q * 4 + 0], 0.f);
        float h1 = fmaxf(v.y + sb1[q * 4 + 1], 0.f);
        float h2 = fmaxf(v.z + sb1[q * 4 + 2], 0.f);
        float h3 = fmaxf(v.w + sb1[q * 4 + 3], 0.f);
        p0 += h0 * sW2[(q * 4 + 0) * 2 + 0] + h1 * sW2[(q * 4 + 1) * 2 + 0]
            + h2 * sW2[(q * 4 + 2) * 2 + 0] + h3 * sW2[(q * 4 + 3) * 2 + 0];
        p1 += h0 * sW2[(q * 4 + 0) * 2 + 1] + h1 * sW2[(q * 4 + 1) * 2 + 1]
            + h2 * sW2[(q * 4 + 2) * 2 + 1] + h3 * sW2[(q * 4 + 3) * 2 + 1];
    }
    float dv = g_deg[i];
    float q0 = p0 * dv, q1 = p1 * dv;
    g_p2[(size_t)i * 2 + 0] = q0;
    g_p2[(size_t)i * 2 + 1] = q1;
    out[(size_t)i * 2 + 0] = sb2[0] + q0 * dv;
    out[(size_t)i * 2 + 1] = sb2[1] + q1 * dv;
}

// ---- layer 2 scatter: out[d] += p2[s] * dinv[d] ----------------------------
__global__ void k_scatter2(const int* __restrict__ src,
                           const int* __restrict__ dst, int E,
                           float* __restrict__ out) {
    int e = blockIdx.x * blockDim.x + threadIdx.x;
    if (e >= E) return;
    int s = __ldg(&src[e]);
    int d = __ldg(&dst[e]);
    float c = __ldg((const float*)&g_deg[d]);
    float2 p = *(const float2*)(g_p2 + (size_t)s * 2);
    red_add_v2(out + (size_t)d * 2, p.x * c, p.y * c);
}

extern "C" void kernel_launch(void* const* d_in, const int* in_sizes, int n_in,
                              void* d_out, int out_size) {
    const float* x   = (const float*)d_in[0];
    const int*   ei  = (const int*)d_in[1];
    const float* W1  = (const float*)d_in[2];
    const float* b1  = (const float*)d_in[3];
    const float* W2  = (const float*)d_in[4];
    const float* b2  = (const float*)d_in[5];
    float*       out = (float*)d_out;

    int n = in_sizes[0] / D_IN;
    int E = in_sizes[1] / 2;
    const int* src = ei;
    const int* dst = ei + E;

    k_init_deg<<<(n + 255) / 256, 256>>>(n);
    k_deg     <<<(E + 255) / 256, 256>>>(dst, E);
    k_dinv    <<<(n + 255) / 256, 256>>>(n);
    k_gemm1   <<<(n + 63) / 64, 256>>>(x, W1, n);
    long long work1 = (long long)E * 8;
    k_scatter1<<<(int)((work1 + 255) / 256), 256>>>(src, dst, (long long)E);
    k_layer2  <<<(n + 255) / 256, 256>>>(b1, W2, b2, out, n);
    k_scatter2<<<(E + 255) / 256, 256>>>(src, dst, E, out);
}

// round 7
// speedup vs baseline: 1.0980x; 1.0349x over previous
#include <cuda_runtime.h>
#include <cstddef>

// GCN 2-layer via per-call CSR build + gather (no fp atomics in aggregation).
// N=100000, E=3.2M, DIN=128, DH=32, DOUT=2. edge_index is int32.

static constexpr int NMAX  = 100000;
static constexpr long long EMAX = 3300000;
static constexpr int D_IN  = 128;
static constexpr int D_H   = 32;
static constexpr int D_OUT = 2;
static constexpr int SCAN_BLK = 2048;      // elements per scan block (256 thr x 8)

__device__ __align__(16) float g_dinv[NMAX];
__device__ __align__(16) float g_m1s [(size_t)NMAX * D_H];   // (x@W1)*dinv[row]
__device__ __align__(16) float g_p2  [(size_t)NMAX * D_OUT]; // (relu(agg1+b1)@W2)*dinv
__device__ int   g_cnt[NMAX];
__device__ int   g_off[NMAX];
__device__ int   g_cur[NMAX];
__device__ int   g_adj[EMAX];              // src indices grouped by dst
__device__ int   g_bsum[(NMAX + SCAN_BLK - 1) / SCAN_BLK];

// ---- CSR build --------------------------------------------------------------
__global__ void k_zero(int n) {
    int i = blockIdx.x * blockDim.x + threadIdx.x;
    if (i < n) g_cnt[i] = 0;
}

__global__ void k_count(const int* __restrict__ dst, int E) {
    int e = blockIdx.x * blockDim.x + threadIdx.x;
    if (e < E) atomicAdd(&g_cnt[dst[e]], 1);
}

// Per-block exclusive scan over 2048 counts (256 thr x 8 serial + smem scan).
__global__ void __launch_bounds__(256) k_part(int n) {
    __shared__ int sp[256];
    int base = blockIdx.x * SCAN_BLK + threadIdx.x * 8;
    int v[8]; int s = 0;
    #pragma unroll
    for (int j = 0; j < 8; j++) {
        int i = base + j;
        v[j] = (i < n) ? g_cnt[i] : 0;
        s += v[j];
    }
    sp[threadIdx.x] = s; __syncthreads();
    for (int ofs = 1; ofs < 256; ofs <<= 1) {
        int t = (threadIdx.x >= ofs) ? sp[threadIdx.x - ofs] : 0;
        __syncthreads();
        sp[threadIdx.x] += t;
        __syncthreads();
    }
    int excl = threadIdx.x ? sp[threadIdx.x - 1] : 0;
    #pragma unroll
    for (int j = 0; j < 8; j++) {
        int i = base + j;
        if (i < n) { g_off[i] = excl; excl += v[j]; }
    }
    if (threadIdx.x == 255) g_bsum[blockIdx.x] = sp[255];
}

__global__ void k_scanb(int nb) {   // serial exclusive scan of <=50 block sums
    if (threadIdx.x == 0 && blockIdx.x == 0) {
        int run = 0;
        for (int b = 0; b < nb; b++) { int t = g_bsum[b]; g_bsum[b] = run; run += t; }
    }
}

__global__ void k_finoff(int n) {
    int i = blockIdx.x * blockDim.x + threadIdx.x;
    if (i >= n) return;
    int off = g_off[i] + g_bsum[i / SCAN_BLK];
    g_off[i] = off;
    g_cur[i] = off;
    g_dinv[i] = rsqrtf((float)g_cnt[i] + 1.0f);   // +1 self loop
}

__global__ void k_fill(const int* __restrict__ src, const int* __restrict__ dst, int E) {
    int e = blockIdx.x * blockDim.x + threadIdx.x;
    if (e >= E) return;
    int d = dst[e];
    int pos = atomicAdd(&g_cur[d], 1);
    g_adj[pos] = src[e];
}

// ---- layer 1 GEMM: m1s = (x@W1)*dinv ---------------------------------------
__global__ void __launch_bounds__(256) k_gemm1(const float* __restrict__ x,
                                               const float* __restrict__ W1, int n) {
    __shared__ float  sWp[D_IN * D_H];       // k-pair interleaved transposed W
    __shared__ float4 sx[8][8][D_IN / 4];
    int tid = threadIdx.x;
    for (int i = tid; i < D_IN * D_H; i += 256) {
        int k = i >> 5, c = i & 31;
        sWp[(k >> 1) * 64 + c * 2 + (k & 1)] = W1[i];
    }
    int warp = tid >> 5, lane = tid & 31;
    int row0 = blockIdx.x * 64 + warp * 8;
    #pragma unroll
    for (int r = 0; r < 8; r++) {
        int row = row0 + r;
        if (row < n)
            sx[warp][r][lane] = ((const float4*)(x + (size_t)row * D_IN))[lane];
    }
    __syncthreads();

    const ulonglong2* sxp = (const ulonglong2*)&sx[warp][0][0];
    const unsigned long long* sWq = (const unsigned long long*)sWp;
    unsigned long long acc[8] = {0ull,0ull,0ull,0ull,0ull,0ull,0ull,0ull};
    #pragma unroll 4
    for (int k4 = 0; k4 < D_IN / 4; k4++) {
        unsigned long long w01 = sWq[(k4 * 2 + 0) * 32 + lane];
        unsigned long long w23 = sWq[(k4 * 2 + 1) * 32 + lane];
        #pragma unroll
        for (int r = 0; r < 8; r++) {
            ulonglong2 xp = sxp[r * 32 + k4];
            asm("fma.rn.f32x2 %0, %1, %2, %0;" : "+l"(acc[r]) : "l"(xp.x), "l"(w01));
            asm("fma.rn.f32x2 %0, %1, %2, %0;" : "+l"(acc[r]) : "l"(xp.y), "l"(w23));
        }
    }
    #pragma unroll
    for (int r = 0; r < 8; r++) {
        int row = row0 + r;
        if (row < n) {
            float lo = __uint_as_float((unsigned)(acc[r] & 0xffffffffull));
            float hi = __uint_as_float((unsigned)(acc[r] >> 32));
            g_m1s[(size_t)row * D_H + lane] = (lo + hi) * g_dinv[row];
        }
    }
}

// ---- fused layer-1 gather + layer-2 transform ------------------------------
// Warp per dst node; lane = feature dim. Per edge: 1 coalesced 128B L2 read.
__global__ void __launch_bounds__(256) k_gather1(const float* __restrict__ b1,
                                                 const float* __restrict__ W2,
                                                 const float* __restrict__ b2,
                                                 float* __restrict__ out, int n) {
    int w = (int)((blockIdx.x * 256 + threadIdx.x) >> 5);
    int lane = threadIdx.x & 31;
    if (w >= n) return;
    int start = g_off[w], cnt = g_cnt[w];
    float dv = g_dinv[w];

    float a0 = 0.f, a1 = 0.f, a2 = 0.f, a3 = 0.f;
    int j = 0;
    for (; j + 32 <= cnt; j += 32) {
        int idx = g_adj[start + j + lane];
        #pragma unroll
        for (int t = 0; t < 32; t += 4) {
            int s0 = __shfl_sync(0xffffffffu, idx, t + 0);
            int s1 = __shfl_sync(0xffffffffu, idx, t + 1);
            int s2 = __shfl_sync(0xffffffffu, idx, t + 2);
            int s3 = __shfl_sync(0xffffffffu, idx, t + 3);
            a0 += g_m1s[(size_t)s0 * D_H + lane];
            a1 += g_m1s[(size_t)s1 * D_H + lane];
            a2 += g_m1s[(size_t)s2 * D_H + lane];
            a3 += g_m1s[(size_t)s3 * D_H + lane];
        }
    }
    if (j < cnt) {
        int rem = cnt - j;
        int idx = (lane < rem) ? g_adj[start + j + lane] : 0;
        for (int t = 0; t < rem; t++) {
            int s = __shfl_sync(0xffffffffu, idx, t);
            a0 += g_m1s[(size_t)s * D_H + lane];
        }
    }
    float acc = (a0 + a1) + (a2 + a3);
    acc += g_m1s[(size_t)w * D_H + lane];          // self loop (m1s = m1*dinv)
    float h = fmaxf(acc * dv + __ldg(&b1[lane]), 0.f);
    float p0 = h * __ldg(&W2[lane * 2 + 0]);
    float p1 = h * __ldg(&W2[lane * 2 + 1]);
    #pragma unroll
    for (int o = 16; o; o >>= 1) {
        p0 += __shfl_xor_sync(0xffffffffu, p0, o);
        p1 += __shfl_xor_sync(0xffffffffu, p1, o);
    }
    if (lane == 0) {
        float q0 = p0 * dv, q1 = p1 * dv;          // pre-scaled by dinv[src]
        g_p2[(size_t)w * 2 + 0] = q0;
        g_p2[(size_t)w * 2 + 1] = q1;
        out[(size_t)w * 2 + 0] = __ldg(&b2[0]) + q0 * dv;   // bias + self loop
        out[(size_t)w * 2 + 1] = __ldg(&b2[1]) + q1 * dv;
    }
}

// ---- layer-2 gather ---------------------------------------------------------
__global__ void __launch_bounds__(256) k_gather2(float* __restrict__ out, int n) {
    int w = (int)((blockIdx.x * 256 + threadIdx.x) >> 5);
    int lane = threadIdx.x & 31;
    if (w >= n) return;
    int start = g_off[w], cnt = g_cnt[w];
    float a0 = 0.f, a1 = 0.f;
    for (int j = lane; j < cnt; j += 32) {
        int s = g_adj[start + j];
        float2 p = *(const float2*)(g_p2 + (size_t)s * 2);
        a0 += p.x; a1 += p.y;
    }
    #pragma unroll
    for (int o = 16; o; o >>= 1) {
        a0 += __shfl_xor_sync(0xffffffffu, a0, o);
        a1 += __shfl_xor_sync(0xffffffffu, a1, o);
    }
    if (lane == 0) {
        float dv = g_dinv[w];
        out[(size_t)w * 2 + 0] += a0 * dv;
        out[(size_t)w * 2 + 1] += a1 * dv;
    }
}

extern "C" void kernel_launch(void* const* d_in, const int* in_sizes, int n_in,
                              void* d_out, int out_size) {
    const float* x   = (const float*)d_in[0];
    const int*   ei  = (const int*)d_in[1];
    const float* W1  = (const float*)d_in[2];
    const float* b1  = (const float*)d_in[3];
    const float* W2  = (const float*)d_in[4];
    const float* b2  = (const float*)d_in[5];
    float*       out = (float*)d_out;

    int n = in_sizes[0] / D_IN;
    int E = in_sizes[1] / 2;
    const int* src = ei;
    const int* dst = ei + E;
    int nb = (n + SCAN_BLK - 1) / SCAN_BLK;

    k_zero   <<<(n + 255) / 256, 256>>>(n);
    k_count  <<<(E + 255) / 256, 256>>>(dst, E);
    k_part   <<<nb, 256>>>(n);
    k_scanb  <<<1, 32>>>(nb);
    k_finoff <<<(n + 255) / 256, 256>>>(n);
    k_fill   <<<(E + 255) / 256, 256>>>(src, dst, E);
    k_gemm1  <<<(n + 63) / 64, 256>>>(x, W1, n);
    k_gather1<<<(n * 32 + 255) / 256, 256>>>(b1, W2, b2, out, n);
    k_gather2<<<(n * 32 + 255) / 256, 256>>>(out, n);
}